// round 7
// baseline (speedup 1.0000x reference)
#include <cuda_runtime.h>
#include <cuda_bf16.h>
#include <cstdint>
#include <math.h>

#define SEQ   128
#define BAT   32
#define EH    512
#define EO    256
#define HID   512
#define G3    1536
#define OUTD  256
#define MROWS (SEQ*BAT)
#define THRESH 1e-6f

typedef unsigned long long ull;
typedef unsigned int u32;

// ---------------- scratch (device globals; no allocation allowed) ----------
__device__ float g_emb[MROWS * EO];          // 4 MB
__device__ float g_xproj[MROWS * G3];        // 25 MB

// ---------------- f32x2 helpers -------------------------------------------
__device__ __forceinline__ ull pack2(float lo, float hi) {
    ull r; asm("mov.b64 %0, {%1, %2};" : "=l"(r) : "f"(lo), "f"(hi)); return r;
}
__device__ __forceinline__ float2 unpack2(ull v) {
    float2 r; asm("mov.b64 {%0, %1}, %2;" : "=f"(r.x), "=f"(r.y) : "l"(v)); return r;
}
__device__ __forceinline__ void fma2(ull& d, ull a, ull b) {
    asm("fma.rn.f32x2 %0, %1, %2, %3;" : "=l"(d) : "l"(a), "l"(b), "l"(d));
}
__device__ __forceinline__ float thr(float v) { return v > THRESH ? v : 0.0f; }

__device__ __forceinline__ u32 smem_u32(const void* p) {
    u32 a;
    asm("{ .reg .u64 t; cvta.to.shared.u64 t, %1; cvt.u32.u64 %0, t; }"
        : "=r"(a) : "l"(p));
    return a;
}
#define CLUSTER_SYNC() do { \
    asm volatile("barrier.cluster.arrive.aligned;" ::: "memory"); \
    asm volatile("barrier.cluster.wait.aligned;"  ::: "memory"); \
} while (0)

// ===========================================================================
// GEMM 1 (fused embedding): emb = thr( thr(W1[tok]+b1) @ W2 + b2 )
//   M=4096 K=512 N=256. Tile 128x64x16, 256 threads, 8x4 micro-tile (f32x2).
// ===========================================================================
__global__ __launch_bounds__(256) void gemm_embed_kernel(
    const int* __restrict__ tok, const float* __restrict__ W1,
    const float* __restrict__ b1, const float* __restrict__ W2,
    const float* __restrict__ b2)
{
    __shared__ __align__(16) float As[16][132];
    __shared__ __align__(16) float Bs[16][68];

    const int bm = blockIdx.x, bn = blockIdx.y;
    const int t  = threadIdx.x;
    const int tx = t & 15, ty = t >> 4;

    const int arow = t >> 2, aseg = t & 3;
    const int tk0 = tok[bm * 128 + arow];
    const int tk1 = tok[bm * 128 + arow + 64];
    const float* w1r0 = W1 + (size_t)tk0 * EH;
    const float* w1r1 = W1 + (size_t)tk1 * EH;
    const int bk = t >> 4, bseg = t & 15;

    ull acc[8][2] = {};

    for (int kt = 0; kt < EH; kt += 16) {
        float4 bb = *(const float4*)(b1 + kt + aseg * 4);
        float4 a0 = *(const float4*)(w1r0 + kt + aseg * 4);
        float4 a1 = *(const float4*)(w1r1 + kt + aseg * 4);
        a0.x = thr(a0.x + bb.x); a0.y = thr(a0.y + bb.y);
        a0.z = thr(a0.z + bb.z); a0.w = thr(a0.w + bb.w);
        a1.x = thr(a1.x + bb.x); a1.y = thr(a1.y + bb.y);
        a1.z = thr(a1.z + bb.z); a1.w = thr(a1.w + bb.w);
        As[aseg * 4 + 0][arow] = a0.x;  As[aseg * 4 + 0][arow + 64] = a1.x;
        As[aseg * 4 + 1][arow] = a0.y;  As[aseg * 4 + 1][arow + 64] = a1.y;
        As[aseg * 4 + 2][arow] = a0.z;  As[aseg * 4 + 2][arow + 64] = a1.z;
        As[aseg * 4 + 3][arow] = a0.w;  As[aseg * 4 + 3][arow + 64] = a1.w;
        *(float4*)&Bs[bk][bseg * 4] =
            *(const float4*)(W2 + (size_t)(kt + bk) * EO + bn * 64 + bseg * 4);
        __syncthreads();
        #pragma unroll
        for (int kk = 0; kk < 16; kk++) {
            float4 av0 = *(const float4*)&As[kk][ty * 8];
            float4 av1 = *(const float4*)&As[kk][ty * 8 + 4];
            ulonglong2 bv = *(const ulonglong2*)&Bs[kk][tx * 4];
            ull a;
            a = pack2(av0.x, av0.x); fma2(acc[0][0], a, bv.x); fma2(acc[0][1], a, bv.y);
            a = pack2(av0.y, av0.y); fma2(acc[1][0], a, bv.x); fma2(acc[1][1], a, bv.y);
            a = pack2(av0.z, av0.z); fma2(acc[2][0], a, bv.x); fma2(acc[2][1], a, bv.y);
            a = pack2(av0.w, av0.w); fma2(acc[3][0], a, bv.x); fma2(acc[3][1], a, bv.y);
            a = pack2(av1.x, av1.x); fma2(acc[4][0], a, bv.x); fma2(acc[4][1], a, bv.y);
            a = pack2(av1.y, av1.y); fma2(acc[5][0], a, bv.x); fma2(acc[5][1], a, bv.y);
            a = pack2(av1.z, av1.z); fma2(acc[6][0], a, bv.x); fma2(acc[6][1], a, bv.y);
            a = pack2(av1.w, av1.w); fma2(acc[7][0], a, bv.x); fma2(acc[7][1], a, bv.y);
        }
        __syncthreads();
    }
    const int m0 = bm * 128 + ty * 8, n0 = bn * 64 + tx * 4;
    #pragma unroll
    for (int i = 0; i < 8; i++) {
        #pragma unroll
        for (int p = 0; p < 2; p++) {
            float2 v = unpack2(acc[i][p]);
            int n = n0 + p * 2;
            v.x = thr(v.x + b2[n]);
            v.y = thr(v.y + b2[n + 1]);
            *(float2*)&g_emb[(size_t)(m0 + i) * EO + n] = v;
        }
    }
}

// ===========================================================================
// GEMM 2 (NT): xproj = emb @ W_ih^T + b_ih   M=4096 K=256 N=1536
//   Tile 128x128x16, 256 threads, 8x8 micro-tile (f32x2).
// ===========================================================================
__global__ __launch_bounds__(256) void gemm_xproj_kernel(
    const float* __restrict__ W_ih, const float* __restrict__ b_ih)
{
    __shared__ __align__(16) float As[16][132];
    __shared__ __align__(16) float Bs[16][132];

    const int bm = blockIdx.x, bn = blockIdx.y;
    const int t  = threadIdx.x;
    const int tx = t & 15, ty = t >> 4;
    const int row = t >> 2, seg = t & 3;

    ull acc[8][4] = {};

    for (int kt = 0; kt < EO; kt += 16) {
        #pragma unroll
        for (int i = 0; i < 2; i++) {
            int r = row + i * 64;
            float4 a4 = *(const float4*)(g_emb + (size_t)(bm * 128 + r) * EO + kt + seg * 4);
            As[seg * 4 + 0][r] = a4.x;
            As[seg * 4 + 1][r] = a4.y;
            As[seg * 4 + 2][r] = a4.z;
            As[seg * 4 + 3][r] = a4.w;
            float4 b4 = *(const float4*)(W_ih + (size_t)(bn * 128 + r) * EO + kt + seg * 4);
            Bs[seg * 4 + 0][r] = b4.x;
            Bs[seg * 4 + 1][r] = b4.y;
            Bs[seg * 4 + 2][r] = b4.z;
            Bs[seg * 4 + 3][r] = b4.w;
        }
        __syncthreads();
        #pragma unroll
        for (int kk = 0; kk < 16; kk++) {
            float4 av0 = *(const float4*)&As[kk][ty * 8];
            float4 av1 = *(const float4*)&As[kk][ty * 8 + 4];
            ulonglong2 b01 = *(const ulonglong2*)&Bs[kk][tx * 8];
            ulonglong2 b23 = *(const ulonglong2*)&Bs[kk][tx * 8 + 4];
            ull a;
            a = pack2(av0.x, av0.x); fma2(acc[0][0], a, b01.x); fma2(acc[0][1], a, b01.y); fma2(acc[0][2], a, b23.x); fma2(acc[0][3], a, b23.y);
            a = pack2(av0.y, av0.y); fma2(acc[1][0], a, b01.x); fma2(acc[1][1], a, b01.y); fma2(acc[1][2], a, b23.x); fma2(acc[1][3], a, b23.y);
            a = pack2(av0.z, av0.z); fma2(acc[2][0], a, b01.x); fma2(acc[2][1], a, b01.y); fma2(acc[2][2], a, b23.x); fma2(acc[2][3], a, b23.y);
            a = pack2(av0.w, av0.w); fma2(acc[3][0], a, b01.x); fma2(acc[3][1], a, b01.y); fma2(acc[3][2], a, b23.x); fma2(acc[3][3], a, b23.y);
            a = pack2(av1.x, av1.x); fma2(acc[4][0], a, b01.x); fma2(acc[4][1], a, b01.y); fma2(acc[4][2], a, b23.x); fma2(acc[4][3], a, b23.y);
            a = pack2(av1.y, av1.y); fma2(acc[5][0], a, b01.x); fma2(acc[5][1], a, b01.y); fma2(acc[5][2], a, b23.x); fma2(acc[5][3], a, b23.y);
            a = pack2(av1.z, av1.z); fma2(acc[6][0], a, b01.x); fma2(acc[6][1], a, b01.y); fma2(acc[6][2], a, b23.x); fma2(acc[6][3], a, b23.y);
            a = pack2(av1.w, av1.w); fma2(acc[7][0], a, b01.x); fma2(acc[7][1], a, b01.y); fma2(acc[7][2], a, b23.x); fma2(acc[7][3], a, b23.y);
        }
        __syncthreads();
    }
    const int m0 = bm * 128 + ty * 8, n0 = bn * 128 + tx * 8;
    #pragma unroll
    for (int i = 0; i < 8; i++) {
        #pragma unroll
        for (int p = 0; p < 4; p++) {
            float2 v = unpack2(acc[i][p]);
            int n = n0 + p * 2;
            v.x += b_ih[n];
            v.y += b_ih[n + 1];
            *(float2*)&g_xproj[(size_t)(m0 + i) * G3 + n] = v;
        }
    }
}

// ===========================================================================
// GRU recurrence: 128 CTAs x 128 threads, clusters of 16 CTAs.
// CTA = (bg 0..7, jg 0..15): owns b in [bg*4,+4), j in [jg*32,+32).
// Cluster (16 CTAs) = one bg group; batch groups independent -> no cross-
// cluster sync. h exchanged via DSMEM push into peers' double-buffered h.
// Thread = (jw 0..31, ks 0..3): all 4 b rows over k-slice kq===ks (mod 4);
// 2-round shfl reduce over ks; thread finalizes b==ks.
// Head GEMM folded into the epilogue (h fully local).
// ===========================================================================
#define CLU    16
#define BPC    4
#define JPC    32
#define WROW   516
#define WS_FLOATS (3 * JPC * WROW)            // 49536 floats (193.5 KB)
#define HBUF_FLOATS (BPC * WROW)              // 2064 floats per buffer
#define GRU_SMEMB ((WS_FLOATS + 2 * HBUF_FLOATS) * 4)   // 214,656 B

__global__ __launch_bounds__(128, 1) __cluster_dims__(CLU, 1, 1)
void gru_kernel(
    const float* __restrict__ W_hh, const float* __restrict__ b_hh,
    const float* __restrict__ W3,   const float* __restrict__ b3,
    float* __restrict__ out)
{
    extern __shared__ __align__(16) float smem[];
    float* w_s = smem;                       // [gate][jw 32][516]
    float* h_s = smem + WS_FLOATS;           // [2][4][516]

    const int t  = threadIdx.x;
    const int bx = blockIdx.x;
    const int jg = bx & 15;                  // == cluster rank
    const int bg = bx >> 4;

    // stage W_hh slice: rows j = jg*32..+32, all 3 gates, K-contiguous
    for (int idx = t; idx < 3 * 32 * 128; idx += 128) {
        int u  = idx & 127;                  // float4 unit within row
        int jr = (idx >> 7) & 31;
        int g  = idx >> 12;
        float4 v = *(const float4*)(W_hh + ((size_t)(g * HID + jg * 32 + jr)) * HID + u * 4);
        *(float4*)(w_s + (g * 32 + jr) * WROW + u * 4) = v;
    }
    // zero both h buffers
    for (int idx = t; idx < 2 * HBUF_FLOATS; idx += 128) h_s[idx] = 0.0f;

    const int ks = t & 3;
    const int jw = t >> 2;                   // 0..31
    const int jglob = jg * 32 + jw;          // 0..511
    const int bglob = bg * 4 + ks;           // global batch row this thread owns

    const float bhr = b_hh[jglob];
    const float bhz = b_hh[HID + jglob];
    const float bhn = b_hh[2 * HID + jglob];

    const float* wr_p = w_s + jw * WROW;
    const float* wz_p = wr_p + 32 * WROW;
    const float* wn_p = wz_p + 32 * WROW;

    // precompute DSMEM push addresses for all 16 ranks (buffer 0 slot)
    u32 raddr[CLU];
    {
        u32 la = smem_u32(h_s) + (u32)(ks * WROW + jglob) * 4u;
        #pragma unroll
        for (int r = 0; r < CLU; r++) {
            asm("mapa.shared::cluster.u32 %0, %1, %2;"
                : "=r"(raddr[r]) : "r"(la), "r"(r));
        }
    }

    CLUSTER_SYNC();   // h zero-init + W staging visible before first step

    for (int step = 0; step < SEQ; step++) {
        const int cb = step & 1;
        const float* hb = h_s + cb * HBUF_FLOATS;
        const u32 push_off = (u32)((cb ^ 1) * HBUF_FLOATS * 4);

        // prefetch this step's xproj (L2) early
        size_t xb = ((size_t)(step * BAT + bglob)) * G3 + jglob;
        float xr = __ldcg(g_xproj + xb);
        float xz = __ldcg(g_xproj + xb + HID);
        float xn = __ldcg(g_xproj + xb + 2 * HID);

        ull acc[4][3];
        #pragma unroll
        for (int m = 0; m < 4; m++) { acc[m][0] = 0; acc[m][1] = 0; acc[m][2] = 0; }

        #pragma unroll 4
        for (int i = 0; i < 32; i++) {
            const int o4 = (i * 4 + ks) * 4;          // float offset, 16B aligned
            ulonglong2 wr = *(const ulonglong2*)(wr_p + o4);
            ulonglong2 wz = *(const ulonglong2*)(wz_p + o4);
            ulonglong2 wn = *(const ulonglong2*)(wn_p + o4);
            #pragma unroll
            for (int m = 0; m < 4; m++) {
                ulonglong2 hv = *(const ulonglong2*)(hb + m * WROW + o4);
                fma2(acc[m][0], hv.x, wr.x); fma2(acc[m][0], hv.y, wr.y);
                fma2(acc[m][1], hv.x, wz.x); fma2(acc[m][1], hv.y, wz.y);
                fma2(acc[m][2], hv.x, wn.x); fma2(acc[m][2], hv.y, wn.y);
            }
        }

        // collapse f32x2 halves, reduce over the 4 ks lanes (xor 1, 2)
        float s[4][3];
        #pragma unroll
        for (int m = 0; m < 4; m++)
            #pragma unroll
            for (int g = 0; g < 3; g++) {
                float2 v = unpack2(acc[m][g]);
                s[m][g] = v.x + v.y;
            }
        #pragma unroll
        for (int off = 1; off <= 2; off <<= 1)
            #pragma unroll
            for (int m = 0; m < 4; m++)
                #pragma unroll
                for (int g = 0; g < 3; g++)
                    s[m][g] += __shfl_xor_sync(0xffffffffu, s[m][g], off);

        float ghr = 0.f, ghz = 0.f, ghn = 0.f;
        #pragma unroll
        for (int m = 0; m < 4; m++)
            if (m == ks) { ghr = s[m][0]; ghz = s[m][1]; ghn = s[m][2]; }
        ghr += bhr; ghz += bhz; ghn += bhn;

        float r = 1.0f / (1.0f + expf(-(xr + ghr)));
        float z = 1.0f / (1.0f + expf(-(xz + ghz)));
        float n = tanhf(xn + r * ghn);
        float hprev = hb[ks * WROW + jglob];
        float hnew  = (1.0f - z) * n + z * hprev;

        // push hnew to every cluster CTA's next h buffer (incl. self)
        #pragma unroll
        for (int rr = 0; rr < CLU; rr++) {
            asm volatile("st.shared::cluster.f32 [%0], %1;"
                         :: "r"(raddr[rr] + push_off), "f"(hnew) : "memory");
        }
        CLUSTER_SYNC();   // orders DSMEM pushes; separates read/write epochs
    }

    // ---- head epilogue: out[b][o] = h[b] . W3[:,o] + b3[o] ----
    // Final h in buffer 0 (SEQ even). CTA: b in [bg*4,+4), o in [jg*16,+16).
    {
        const float* hf = h_s;                // buffer 0
        const int o  = t & 15;                // 0..15
        const int kc = t >> 4;                // 0..7, k-chunk of 64
        float part[4];
        #pragma unroll
        for (int bb = 0; bb < 4; bb++) part[bb] = 0.f;
        for (int kk = kc * 64; kk < kc * 64 + 64; kk++) {
            float w = __ldg(W3 + (size_t)kk * OUTD + jg * 16 + o);
            #pragma unroll
            for (int bb = 0; bb < 4; bb++)
                part[bb] = fmaf(hf[bb * WROW + kk], w, part[bb]);
        }
        float* red = w_s;                     // scratch [8][16][4]
        #pragma unroll
        for (int bb = 0; bb < 4; bb++) red[(kc * 16 + o) * 4 + bb] = part[bb];
        __syncthreads();
        if (t < 64) {
            int oo = t & 15, bb = t >> 4;
            float sum = b3[jg * 16 + oo];
            #pragma unroll
            for (int k2 = 0; k2 < 8; k2++) sum += red[(k2 * 16 + oo) * 4 + bb];
            out[(bg * 4 + bb) * OUTD + jg * 16 + oo] = sum;
        }
    }
    CLUSTER_SYNC();   // no CTA exits while peers may still touch its SMEM
}

// ===========================================================================
extern "C" void kernel_launch(void* const* d_in, const int* in_sizes, int n_in,
                              void* d_out, int out_size)
{
    const int*   input = (const int*)  d_in[0];
    const float* W1    = (const float*)d_in[1];
    const float* b1    = (const float*)d_in[2];
    const float* W2    = (const float*)d_in[3];
    const float* b2    = (const float*)d_in[4];
    const float* W_ih  = (const float*)d_in[5];
    const float* W_hh  = (const float*)d_in[6];
    const float* b_ih  = (const float*)d_in[7];
    const float* b_hh  = (const float*)d_in[8];
    const float* W3    = (const float*)d_in[9];
    const float* b3    = (const float*)d_in[10];
    float* out = (float*)d_out;

    static int configured = 0;
    if (!configured) {
        cudaFuncSetAttribute(gru_kernel,
            cudaFuncAttributeMaxDynamicSharedMemorySize, GRU_SMEMB);
        cudaFuncSetAttribute(gru_kernel,
            cudaFuncAttributeNonPortableClusterSizeAllowed, 1);
        configured = 1;
    }

    dim3 g1(MROWS / 128, EO / 64);
    gemm_embed_kernel<<<g1, 256>>>(input, W1, b1, W2, b2);

    dim3 g2(MROWS / 128, G3 / 128);
    gemm_xproj_kernel<<<g2, 256>>>(W_ih, b_ih);

    gru_kernel<<<128, 128, GRU_SMEMB>>>(W_hh, b_hh, W3, b3, out);
}

// round 8
// speedup vs baseline: 1.3464x; 1.3464x over previous
#include <cuda_runtime.h>
#include <cuda_bf16.h>
#include <cstdint>
#include <math.h>

#define SEQ   128
#define BAT   32
#define EH    512
#define EO    256
#define HID   512
#define G3    1536
#define OUTD  256
#define MROWS (SEQ*BAT)
#define THRESH 1e-6f

typedef unsigned long long ull;
typedef unsigned int u32;

// ---------------- scratch (device globals; no allocation allowed) ----------
__device__ float g_emb[MROWS * EO];          // 4 MB
__device__ float g_xproj[MROWS * G3];        // 25 MB

// ---------------- f32x2 helpers -------------------------------------------
__device__ __forceinline__ ull pack2(float lo, float hi) {
    ull r; asm("mov.b64 %0, {%1, %2};" : "=l"(r) : "f"(lo), "f"(hi)); return r;
}
__device__ __forceinline__ float2 unpack2(ull v) {
    float2 r; asm("mov.b64 {%0, %1}, %2;" : "=f"(r.x), "=f"(r.y) : "l"(v)); return r;
}
__device__ __forceinline__ void fma2(ull& d, ull a, ull b) {
    asm("fma.rn.f32x2 %0, %1, %2, %3;" : "=l"(d) : "l"(a), "l"(b), "l"(d));
}
__device__ __forceinline__ float thr(float v) { return v > THRESH ? v : 0.0f; }

__device__ __forceinline__ u32 smem_u32(const void* p) {
    u32 a;
    asm("{ .reg .u64 t; cvta.to.shared.u64 t, %1; cvt.u32.u64 %0, t; }"
        : "=r"(a) : "l"(p));
    return a;
}
#define CLUSTER_SYNC() do { \
    asm volatile("barrier.cluster.arrive.aligned;" ::: "memory"); \
    asm volatile("barrier.cluster.wait.aligned;"  ::: "memory"); \
} while (0)

// ===========================================================================
// GEMM 1 (fused embedding): emb = thr( thr(W1[tok]+b1) @ W2 + b2 )
//   M=4096 K=512 N=256. Tile 128x64x16, 256 threads, 8x4 micro-tile (f32x2).
// ===========================================================================
__global__ __launch_bounds__(256) void gemm_embed_kernel(
    const int* __restrict__ tok, const float* __restrict__ W1,
    const float* __restrict__ b1, const float* __restrict__ W2,
    const float* __restrict__ b2)
{
    __shared__ __align__(16) float As[16][132];
    __shared__ __align__(16) float Bs[16][68];

    const int bm = blockIdx.x, bn = blockIdx.y;
    const int t  = threadIdx.x;
    const int tx = t & 15, ty = t >> 4;

    const int arow = t >> 2, aseg = t & 3;
    const int tk0 = tok[bm * 128 + arow];
    const int tk1 = tok[bm * 128 + arow + 64];
    const float* w1r0 = W1 + (size_t)tk0 * EH;
    const float* w1r1 = W1 + (size_t)tk1 * EH;
    const int bk = t >> 4, bseg = t & 15;

    ull acc[8][2] = {};

    for (int kt = 0; kt < EH; kt += 16) {
        float4 bb = *(const float4*)(b1 + kt + aseg * 4);
        float4 a0 = *(const float4*)(w1r0 + kt + aseg * 4);
        float4 a1 = *(const float4*)(w1r1 + kt + aseg * 4);
        a0.x = thr(a0.x + bb.x); a0.y = thr(a0.y + bb.y);
        a0.z = thr(a0.z + bb.z); a0.w = thr(a0.w + bb.w);
        a1.x = thr(a1.x + bb.x); a1.y = thr(a1.y + bb.y);
        a1.z = thr(a1.z + bb.z); a1.w = thr(a1.w + bb.w);
        As[aseg * 4 + 0][arow] = a0.x;  As[aseg * 4 + 0][arow + 64] = a1.x;
        As[aseg * 4 + 1][arow] = a0.y;  As[aseg * 4 + 1][arow + 64] = a1.y;
        As[aseg * 4 + 2][arow] = a0.z;  As[aseg * 4 + 2][arow + 64] = a1.z;
        As[aseg * 4 + 3][arow] = a0.w;  As[aseg * 4 + 3][arow + 64] = a1.w;
        *(float4*)&Bs[bk][bseg * 4] =
            *(const float4*)(W2 + (size_t)(kt + bk) * EO + bn * 64 + bseg * 4);
        __syncthreads();
        #pragma unroll
        for (int kk = 0; kk < 16; kk++) {
            float4 av0 = *(const float4*)&As[kk][ty * 8];
            float4 av1 = *(const float4*)&As[kk][ty * 8 + 4];
            ulonglong2 bv = *(const ulonglong2*)&Bs[kk][tx * 4];
            ull a;
            a = pack2(av0.x, av0.x); fma2(acc[0][0], a, bv.x); fma2(acc[0][1], a, bv.y);
            a = pack2(av0.y, av0.y); fma2(acc[1][0], a, bv.x); fma2(acc[1][1], a, bv.y);
            a = pack2(av0.z, av0.z); fma2(acc[2][0], a, bv.x); fma2(acc[2][1], a, bv.y);
            a = pack2(av0.w, av0.w); fma2(acc[3][0], a, bv.x); fma2(acc[3][1], a, bv.y);
            a = pack2(av1.x, av1.x); fma2(acc[4][0], a, bv.x); fma2(acc[4][1], a, bv.y);
            a = pack2(av1.y, av1.y); fma2(acc[5][0], a, bv.x); fma2(acc[5][1], a, bv.y);
            a = pack2(av1.z, av1.z); fma2(acc[6][0], a, bv.x); fma2(acc[6][1], a, bv.y);
            a = pack2(av1.w, av1.w); fma2(acc[7][0], a, bv.x); fma2(acc[7][1], a, bv.y);
        }
        __syncthreads();
    }
    const int m0 = bm * 128 + ty * 8, n0 = bn * 64 + tx * 4;
    #pragma unroll
    for (int i = 0; i < 8; i++) {
        #pragma unroll
        for (int p = 0; p < 2; p++) {
            float2 v = unpack2(acc[i][p]);
            int n = n0 + p * 2;
            v.x = thr(v.x + b2[n]);
            v.y = thr(v.y + b2[n + 1]);
            *(float2*)&g_emb[(size_t)(m0 + i) * EO + n] = v;
        }
    }
}

// ===========================================================================
// GEMM 2 (NT): xproj = emb @ W_ih^T + b_ih   M=4096 K=256 N=1536
//   Tile 128x128x16, 256 threads, 8x8 micro-tile (f32x2).
// ===========================================================================
__global__ __launch_bounds__(256) void gemm_xproj_kernel(
    const float* __restrict__ W_ih, const float* __restrict__ b_ih)
{
    __shared__ __align__(16) float As[16][132];
    __shared__ __align__(16) float Bs[16][132];

    const int bm = blockIdx.x, bn = blockIdx.y;
    const int t  = threadIdx.x;
    const int tx = t & 15, ty = t >> 4;
    const int row = t >> 2, seg = t & 3;

    ull acc[8][4] = {};

    for (int kt = 0; kt < EO; kt += 16) {
        #pragma unroll
        for (int i = 0; i < 2; i++) {
            int r = row + i * 64;
            float4 a4 = *(const float4*)(g_emb + (size_t)(bm * 128 + r) * EO + kt + seg * 4);
            As[seg * 4 + 0][r] = a4.x;
            As[seg * 4 + 1][r] = a4.y;
            As[seg * 4 + 2][r] = a4.z;
            As[seg * 4 + 3][r] = a4.w;
            float4 b4 = *(const float4*)(W_ih + (size_t)(bn * 128 + r) * EO + kt + seg * 4);
            Bs[seg * 4 + 0][r] = b4.x;
            Bs[seg * 4 + 1][r] = b4.y;
            Bs[seg * 4 + 2][r] = b4.z;
            Bs[seg * 4 + 3][r] = b4.w;
        }
        __syncthreads();
        #pragma unroll
        for (int kk = 0; kk < 16; kk++) {
            float4 av0 = *(const float4*)&As[kk][ty * 8];
            float4 av1 = *(const float4*)&As[kk][ty * 8 + 4];
            ulonglong2 b01 = *(const ulonglong2*)&Bs[kk][tx * 8];
            ulonglong2 b23 = *(const ulonglong2*)&Bs[kk][tx * 8 + 4];
            ull a;
            a = pack2(av0.x, av0.x); fma2(acc[0][0], a, b01.x); fma2(acc[0][1], a, b01.y); fma2(acc[0][2], a, b23.x); fma2(acc[0][3], a, b23.y);
            a = pack2(av0.y, av0.y); fma2(acc[1][0], a, b01.x); fma2(acc[1][1], a, b01.y); fma2(acc[1][2], a, b23.x); fma2(acc[1][3], a, b23.y);
            a = pack2(av0.z, av0.z); fma2(acc[2][0], a, b01.x); fma2(acc[2][1], a, b01.y); fma2(acc[2][2], a, b23.x); fma2(acc[2][3], a, b23.y);
            a = pack2(av0.w, av0.w); fma2(acc[3][0], a, b01.x); fma2(acc[3][1], a, b01.y); fma2(acc[3][2], a, b23.x); fma2(acc[3][3], a, b23.y);
            a = pack2(av1.x, av1.x); fma2(acc[4][0], a, b01.x); fma2(acc[4][1], a, b01.y); fma2(acc[4][2], a, b23.x); fma2(acc[4][3], a, b23.y);
            a = pack2(av1.y, av1.y); fma2(acc[5][0], a, b01.x); fma2(acc[5][1], a, b01.y); fma2(acc[5][2], a, b23.x); fma2(acc[5][3], a, b23.y);
            a = pack2(av1.z, av1.z); fma2(acc[6][0], a, b01.x); fma2(acc[6][1], a, b01.y); fma2(acc[6][2], a, b23.x); fma2(acc[6][3], a, b23.y);
            a = pack2(av1.w, av1.w); fma2(acc[7][0], a, b01.x); fma2(acc[7][1], a, b01.y); fma2(acc[7][2], a, b23.x); fma2(acc[7][3], a, b23.y);
        }
        __syncthreads();
    }
    const int m0 = bm * 128 + ty * 8, n0 = bn * 128 + tx * 8;
    #pragma unroll
    for (int i = 0; i < 8; i++) {
        #pragma unroll
        for (int p = 0; p < 4; p++) {
            float2 v = unpack2(acc[i][p]);
            int n = n0 + p * 2;
            v.x += b_ih[n];
            v.y += b_ih[n + 1];
            *(float2*)&g_xproj[(size_t)(m0 + i) * G3 + n] = v;
        }
    }
}

// ===========================================================================
// GRU recurrence: 64 CTAs x 256 threads, 4 clusters of 16 CTAs.
// Cluster = one bg group of 8 batch rows; CTA = (bg 0..3, jg 0..15):
// owns b in [bg*8,+8), j in [jg*32,+32). Only 4 clusters -> they always
// co-schedule (no wave serialization regardless of die/GPC packing).
// Thread = (jw 0..31, bh 0..1, ks 0..3): 4 b rows (bh*4..+4) over k-slice
// kq===ks (mod 4); 2-round shfl reduce over ks; finalizes b = bh*4+ks.
// h exchanged via DSMEM push into all 16 peers' double-buffered h.
// Head GEMM folded into the epilogue (h fully local).
// ===========================================================================
#define CLU    16
#define BPC    8
#define JPC    32
#define WROW   516
#define WS_FLOATS (3 * JPC * WROW)            // 49536 floats (193.5 KB)
#define HBUF_FLOATS (BPC * WROW)              // 4128 floats per buffer
#define GRU_SMEMB ((WS_FLOATS + 2 * HBUF_FLOATS) * 4)   // 231,168 B

__global__ __launch_bounds__(256, 1) __cluster_dims__(CLU, 1, 1)
void gru_kernel(
    const float* __restrict__ W_hh, const float* __restrict__ b_hh,
    const float* __restrict__ W3,   const float* __restrict__ b3,
    float* __restrict__ out)
{
    extern __shared__ __align__(16) float smem[];
    float* w_s = smem;                       // [gate][jw 32][516]
    float* h_s = smem + WS_FLOATS;           // [2][8][516]

    const int t  = threadIdx.x;
    const int bx = blockIdx.x;
    const int jg = bx & 15;                  // == cluster rank
    const int bg = bx >> 4;                  // 0..3

    // stage W_hh slice: rows j = jg*32..+32, all 3 gates, K-contiguous
    for (int idx = t; idx < 3 * 32 * 128; idx += 256) {
        int u  = idx & 127;                  // float4 unit within row
        int jr = (idx >> 7) & 31;
        int g  = idx >> 12;
        float4 v = *(const float4*)(W_hh + ((size_t)(g * HID + jg * 32 + jr)) * HID + u * 4);
        *(float4*)(w_s + (g * 32 + jr) * WROW + u * 4) = v;
    }
    // zero both h buffers
    for (int idx = t; idx < 2 * HBUF_FLOATS; idx += 256) h_s[idx] = 0.0f;

    const int ks = t & 3;
    const int bh = (t >> 2) & 1;
    const int jw = t >> 3;                   // 0..31
    const int jglob = jg * 32 + jw;          // 0..511
    const int bloc  = bh * 4 + ks;           // local b row this thread outputs
    const int bglob = bg * 8 + bloc;         // global batch row

    const float bhr = b_hh[jglob];
    const float bhz = b_hh[HID + jglob];
    const float bhn = b_hh[2 * HID + jglob];

    const float* wr_p = w_s + jw * WROW;
    const float* wz_p = wr_p + 32 * WROW;
    const float* wn_p = wz_p + 32 * WROW;

    // precompute DSMEM push addresses for all 16 ranks (buffer 0 slot)
    u32 raddr[CLU];
    {
        u32 la = smem_u32(h_s) + (u32)(bloc * WROW + jglob) * 4u;
        #pragma unroll
        for (int r = 0; r < CLU; r++) {
            asm("mapa.shared::cluster.u32 %0, %1, %2;"
                : "=r"(raddr[r]) : "r"(la), "r"(r));
        }
    }

    CLUSTER_SYNC();   // h zero-init + W staging visible before first step

    for (int step = 0; step < SEQ; step++) {
        const int cb = step & 1;
        const float* hb = h_s + cb * HBUF_FLOATS + bh * 4 * WROW;
        const u32 push_off = (u32)((cb ^ 1) * HBUF_FLOATS * 4);

        // prefetch this step's xproj (L2) early
        size_t xb = ((size_t)(step * BAT + bglob)) * G3 + jglob;
        float xr = __ldcg(g_xproj + xb);
        float xz = __ldcg(g_xproj + xb + HID);
        float xn = __ldcg(g_xproj + xb + 2 * HID);

        ull acc[4][3];
        #pragma unroll
        for (int m = 0; m < 4; m++) { acc[m][0] = 0; acc[m][1] = 0; acc[m][2] = 0; }

        #pragma unroll 4
        for (int i = 0; i < 32; i++) {
            const int o4 = (i * 4 + ks) * 4;          // float offset, 16B aligned
            ulonglong2 wr = *(const ulonglong2*)(wr_p + o4);
            ulonglong2 wz = *(const ulonglong2*)(wz_p + o4);
            ulonglong2 wn = *(const ulonglong2*)(wn_p + o4);
            #pragma unroll
            for (int m = 0; m < 4; m++) {
                ulonglong2 hv = *(const ulonglong2*)(hb + m * WROW + o4);
                fma2(acc[m][0], hv.x, wr.x); fma2(acc[m][0], hv.y, wr.y);
                fma2(acc[m][1], hv.x, wz.x); fma2(acc[m][1], hv.y, wz.y);
                fma2(acc[m][2], hv.x, wn.x); fma2(acc[m][2], hv.y, wn.y);
            }
        }

        // collapse f32x2 halves, reduce over the 4 ks lanes (xor 1, 2)
        float s[4][3];
        #pragma unroll
        for (int m = 0; m < 4; m++)
            #pragma unroll
            for (int g = 0; g < 3; g++) {
                float2 v = unpack2(acc[m][g]);
                s[m][g] = v.x + v.y;
            }
        #pragma unroll
        for (int off = 1; off <= 2; off <<= 1)
            #pragma unroll
            for (int m = 0; m < 4; m++)
                #pragma unroll
                for (int g = 0; g < 3; g++)
                    s[m][g] += __shfl_xor_sync(0xffffffffu, s[m][g], off);

        float ghr = 0.f, ghz = 0.f, ghn = 0.f;
        #pragma unroll
        for (int m = 0; m < 4; m++)
            if (m == ks) { ghr = s[m][0]; ghz = s[m][1]; ghn = s[m][2]; }
        ghr += bhr; ghz += bhz; ghn += bhn;

        float r = 1.0f / (1.0f + expf(-(xr + ghr)));
        float z = 1.0f / (1.0f + expf(-(xz + ghz)));
        float n = tanhf(xn + r * ghn);
        float hprev = hb[ks * WROW + jglob];
        float hnew  = (1.0f - z) * n + z * hprev;

        // push hnew to every cluster CTA's next h buffer (incl. self)
        #pragma unroll
        for (int rr = 0; rr < CLU; rr++) {
            asm volatile("st.shared::cluster.f32 [%0], %1;"
                         :: "r"(raddr[rr] + push_off), "f"(hnew) : "memory");
        }
        CLUSTER_SYNC();   // orders DSMEM pushes; separates read/write epochs
    }

    // ---- head epilogue: out[b][o] = h[b] . W3[:,o] + b3[o] ----
    // Final h in buffer 0 (SEQ even). CTA: b in [bg*8,+8), o in [jg*16,+16).
    {
        const float* hf = h_s;                // buffer 0
        const int o  = t & 15;                // 0..15
        const int kc = t >> 4;                // 0..15, k-chunk of 32
        float part[8];
        #pragma unroll
        for (int bb = 0; bb < 8; bb++) part[bb] = 0.f;
        for (int kk = kc * 32; kk < kc * 32 + 32; kk++) {
            float w = __ldg(W3 + (size_t)kk * OUTD + jg * 16 + o);
            #pragma unroll
            for (int bb = 0; bb < 8; bb++)
                part[bb] = fmaf(hf[bb * WROW + kk], w, part[bb]);
        }
        float* red = w_s;                     // scratch [16][16][8]
        #pragma unroll
        for (int bb = 0; bb < 8; bb++) red[(kc * 16 + o) * 8 + bb] = part[bb];
        __syncthreads();
        if (t < 128) {
            int oo = t & 15, bb = t >> 4;
            float sum = b3[jg * 16 + oo];
            #pragma unroll
            for (int k2 = 0; k2 < 16; k2++) sum += red[(k2 * 16 + oo) * 8 + bb];
            out[(bg * 8 + bb) * OUTD + jg * 16 + oo] = sum;
        }
    }
    CLUSTER_SYNC();   // no CTA exits while peers may still touch its SMEM
}

// ===========================================================================
extern "C" void kernel_launch(void* const* d_in, const int* in_sizes, int n_in,
                              void* d_out, int out_size)
{
    const int*   input = (const int*)  d_in[0];
    const float* W1    = (const float*)d_in[1];
    const float* b1    = (const float*)d_in[2];
    const float* W2    = (const float*)d_in[3];
    const float* b2    = (const float*)d_in[4];
    const float* W_ih  = (const float*)d_in[5];
    const float* W_hh  = (const float*)d_in[6];
    const float* b_ih  = (const float*)d_in[7];
    const float* b_hh  = (const float*)d_in[8];
    const float* W3    = (const float*)d_in[9];
    const float* b3    = (const float*)d_in[10];
    float* out = (float*)d_out;

    static int configured = 0;
    if (!configured) {
        cudaFuncSetAttribute(gru_kernel,
            cudaFuncAttributeMaxDynamicSharedMemorySize, GRU_SMEMB);
        cudaFuncSetAttribute(gru_kernel,
            cudaFuncAttributeNonPortableClusterSizeAllowed, 1);
        configured = 1;
    }

    dim3 g1(MROWS / 128, EO / 64);
    gemm_embed_kernel<<<g1, 256>>>(input, W1, b1, W2, b2);

    dim3 g2(MROWS / 128, G3 / 128);
    gemm_xproj_kernel<<<g2, 256>>>(W_ih, b_ih);

    gru_kernel<<<64, 256, GRU_SMEMB>>>(W_hh, b_hh, W3, b3, out);
}